// round 10
// baseline (speedup 1.0000x reference)
#include <cuda_runtime.h>
#include <cuda_fp16.h>
#include <cstdint>

// Problem (fixed): B=4,N=2048,Fin=128,H=4,Fout=32.
// Identity: softmax(scores,m).sum(m)==1  =>  out = (1+self_weight)*(x @ W).
// adj, att are dead inputs.
//
// R10: A-direct HMMA. x is loaded straight into m16n8k16 A-fragments with
// sector-perfect LDG.64 (lane l: rows gp/gp+8, cols 2tq/2tq+8), converted
// fp32->fp16 in registers. No A smem, no A ldsm, barrier only guards W.
// W: exact fp16 hi/lo split in smem + ldsm.trans (R8 path).
// out ~= xh*(wh+wl)  -- same arithmetic as R8 (rel_err 2.08e-4).
// Software pipeline: A k-step ks+4 prefetched while ks computes.

#define MDIM 8192
#define KDIM 128
#define NDIM 128
#define TM 64
#define TN 64
#define BSTRIDE 144   // B smem row: 64 fp16 = 128B data + 16 pad

#define SMEM_BH 0
#define SMEM_BL (SMEM_BH + KDIM * BSTRIDE)      // 18432
#define SMEM_TOTAL (SMEM_BL + KDIM * BSTRIDE)   // 36864

__device__ __forceinline__ uint32_t smem_u32(const void* p) {
    uint32_t a;
    asm("{ .reg .u64 t; cvta.to.shared.u64 t, %1; cvt.u32.u64 %0, t; }"
        : "=r"(a) : "l"(p));
    return a;
}

__device__ __forceinline__ void ldsm4t(uint32_t r[4], uint32_t addr) {
    asm volatile("ldmatrix.sync.aligned.m8n8.x4.trans.shared.b16 {%0,%1,%2,%3}, [%4];"
                 : "=r"(r[0]), "=r"(r[1]), "=r"(r[2]), "=r"(r[3]) : "r"(addr));
}

__device__ __forceinline__ void mma_f16(float c[4], const uint32_t a[4],
                                        uint32_t b0, uint32_t b1) {
    asm volatile(
        "mma.sync.aligned.m16n8k16.row.col.f32.f16.f16.f32 "
        "{%0,%1,%2,%3}, {%4,%5,%6,%7}, {%8,%9}, {%0,%1,%2,%3};"
        : "+f"(c[0]), "+f"(c[1]), "+f"(c[2]), "+f"(c[3])
        : "r"(a[0]), "r"(a[1]), "r"(a[2]), "r"(a[3]), "r"(b0), "r"(b1));
}

__device__ __forceinline__ uint32_t h2_pack(float a, float b) {
    __half2 h = __float22half2_rn(make_float2(a, b));
    return *reinterpret_cast<uint32_t*>(&h);
}
__device__ __forceinline__ uint32_t h2_of(float2 f) { return h2_pack(f.x, f.y); }

__global__ __launch_bounds__(256, 2)
void gat_hmma_kernel(const float* __restrict__ x,
                     const float* __restrict__ W,
                     const float* __restrict__ self_weight,
                     float* __restrict__ out) {
    extern __shared__ char smem[];
    const uint32_t sbase = smem_u32(smem);
    const int tid = threadIdx.x;
    const int wid = tid >> 5;
    const int lid = tid & 31;

    const int bcol = blockIdx.x & 1;
    const int brow = blockIdx.x >> 1;
    const int row0 = brow * TM;
    const int col0 = bcol * TN;

    const float s = 1.0f + self_weight[0];

    // warp tile: 16 rows x 32 cols (4x2 warp grid)
    const int wm = (wid >> 1) * 16;     // 0,16,32,48
    const int wn = (wid & 1) * 32;      // 0,32

    // ---- W loads first (they gate the only barrier) ----
    float4 fb[8];
    #pragma unroll
    for (int r = 0; r < 8; r++) {
        int g  = tid + r * 256;
        int k  = g >> 4;                  // 0..127
        int n4 = g & 15;
        fb[r] = *(const float4*)&W[(size_t)k * NDIM + col0 + n4 * 4];
    }

    // ---- A fragment direct-load setup ----
    const int gp = lid >> 2;              // 0..7
    const int tq = lid & 3;               // 0..3
    const float* arow0 = x + (size_t)(row0 + wm + gp) * KDIM + 2 * tq;
    const float* arow8 = arow0 + (size_t)8 * KDIM;

    // in-flight fp32 fragment sources, 4 k-steps ahead
    float2 f0[8], f1[8], f2[8], f3[8];
    #pragma unroll
    for (int ks = 0; ks < 4; ks++) {
        f0[ks] = *(const float2*)(arow0 + 16 * ks);
        f2[ks] = *(const float2*)(arow0 + 16 * ks + 8);
        f1[ks] = *(const float2*)(arow8 + 16 * ks);
        f3[ks] = *(const float2*)(arow8 + 16 * ks + 8);
    }

    // ---- W: exact fp16 hi/lo split into smem ----
    #pragma unroll
    for (int r = 0; r < 8; r++) {
        int g  = tid + r * 256;
        int k  = g >> 4;
        int n4 = g & 15;
        float4 f = fb[r];
        __half2 h01 = __float22half2_rn(make_float2(f.x, f.y));
        __half2 h23 = __float22half2_rn(make_float2(f.z, f.w));
        uint2 hp, lp;
        hp.x = *reinterpret_cast<uint32_t*>(&h01);
        hp.y = *reinterpret_cast<uint32_t*>(&h23);
        lp.x = h2_pack(f.x - __half2float(h01.x), f.y - __half2float(h01.y));
        lp.y = h2_pack(f.z - __half2float(h23.x), f.w - __half2float(h23.y));
        *(uint2*)(smem + SMEM_BH + k * BSTRIDE + n4 * 8) = hp;
        *(uint2*)(smem + SMEM_BL + k * BSTRIDE + n4 * 8) = lp;
    }
    __syncthreads();

    // ---- accumulators ----
    float t0[4][4], t1[4][4];
    #pragma unroll
    for (int j = 0; j < 4; j++)
        #pragma unroll
        for (int e = 0; e < 4; e++) { t0[j][e] = 0.f; t1[j][e] = 0.f; }

    // B ldsm.trans addressing (R8-proven)
    uint32_t bAddr[2];
    #pragma unroll
    for (int p = 0; p < 2; p++)
        bAddr[p] = sbase + SMEM_BH
            + (8 * ((lid >> 3) & 1) + (lid & 7)) * BSTRIDE
            + (wn + 16 * p + 8 * (lid >> 4)) * 2;
    const uint32_t dBL = SMEM_BL - SMEM_BH;

    // ---- main loop: compute ks, prefetch ks+4 ----
    #pragma unroll
    for (int ks = 0; ks < 8; ks++) {
        if (ks < 4) {
            const int kp = ks + 4;
            f0[kp] = *(const float2*)(arow0 + 16 * kp);
            f2[kp] = *(const float2*)(arow0 + 16 * kp + 8);
            f1[kp] = *(const float2*)(arow8 + 16 * kp);
            f3[kp] = *(const float2*)(arow8 + 16 * kp + 8);
        }

        uint32_t ah[4];
        ah[0] = h2_of(f0[ks]);
        ah[1] = h2_of(f1[ks]);
        ah[2] = h2_of(f2[ks]);
        ah[3] = h2_of(f3[ks]);

        const uint32_t bko = ks * 16 * BSTRIDE;
        uint32_t bh[2][4], bl[2][4];
        #pragma unroll
        for (int p = 0; p < 2; p++) {
            ldsm4t(bh[p], bAddr[p] + bko);
            ldsm4t(bl[p], bAddr[p] + bko + dBL);
        }

        #pragma unroll
        for (int nt = 0; nt < 4; nt++) {
            const int p = nt >> 1, q = (nt & 1) * 2;
            mma_f16(t0[nt], ah, bh[p][q], bh[p][q + 1]);  // xh*wh
            mma_f16(t1[nt], ah, bl[p][q], bl[p][q + 1]);  // xh*wl
        }
    }

    // ---- epilogue: combine, scale, store ----
    #pragma unroll
    for (int nt = 0; nt < 4; nt++) {
        const int r0 = row0 + wm + (lid >> 2);
        const int c  = col0 + wn + 8 * nt + 2 * (lid & 3);
        float2 s0 = {(t0[nt][0] + t1[nt][0]) * s, (t0[nt][1] + t1[nt][1]) * s};
        float2 s1 = {(t0[nt][2] + t1[nt][2]) * s, (t0[nt][3] + t1[nt][3]) * s};
        *(float2*)&out[(size_t)r0 * NDIM + c]       = s0;
        *(float2*)&out[(size_t)(r0 + 8) * NDIM + c] = s1;
    }
}

extern "C" void kernel_launch(void* const* d_in, const int* in_sizes, int n_in,
                              void* d_out, int out_size) {
    // metadata order: x, adj (UNUSED), W, att (UNUSED), self_weight
    const float* x  = (const float*)d_in[0];
    const float* W  = (const float*)d_in[2];
    const float* sw = (const float*)d_in[4];
    float* out      = (float*)d_out;

    cudaFuncSetAttribute(gat_hmma_kernel,
                         cudaFuncAttributeMaxDynamicSharedMemorySize, SMEM_TOTAL);

    dim3 grid((MDIM / TM) * (NDIM / TN));         // 128 * 2 = 256 blocks
    gat_hmma_kernel<<<grid, 256, SMEM_TOTAL>>>(x, W, sw, out);
}

// round 11
// speedup vs baseline: 1.2294x; 1.2294x over previous
#include <cuda_runtime.h>
#include <cuda_fp16.h>
#include <cstdint>

// Problem (fixed): B=4,N=2048,Fin=128,H=4,Fout=32.
// Identity: softmax(scores,m).sum(m)==1  =>  out = (1+self_weight)*(x @ W).
// adj, att are dead inputs.
//
// R11: R8 math (out ~= xh*(wh+wl), x fp16, W exact fp16 hi/lo split), but
// warp tile 32x32 with 4 warps/block (128 thr): B fragments reused across
// 2 m-tiles -> smem ldsm traffic per output cut ~40% (L1 was the top pipe
// in every profile R5-R10).

#define MDIM 8192
#define KDIM 128
#define NDIM 128
#define TM 64
#define TN 64
#define ASTRIDE 272   // A smem row: 128 fp16 = 256B data + 16 pad
#define BSTRIDE 144   // B smem row: 64 fp16 = 128B data + 16 pad

#define SMEM_A  0
#define SMEM_BH (SMEM_A + TM * ASTRIDE)         // 17408
#define SMEM_BL (SMEM_BH + KDIM * BSTRIDE)      // 35840
#define SMEM_TOTAL (SMEM_BL + KDIM * BSTRIDE)   // 54272

__device__ __forceinline__ uint32_t smem_u32(const void* p) {
    uint32_t a;
    asm("{ .reg .u64 t; cvta.to.shared.u64 t, %1; cvt.u32.u64 %0, t; }"
        : "=r"(a) : "l"(p));
    return a;
}

__device__ __forceinline__ void ldsm4(uint32_t r[4], uint32_t addr) {
    asm volatile("ldmatrix.sync.aligned.m8n8.x4.shared.b16 {%0,%1,%2,%3}, [%4];"
                 : "=r"(r[0]), "=r"(r[1]), "=r"(r[2]), "=r"(r[3]) : "r"(addr));
}
__device__ __forceinline__ void ldsm4t(uint32_t r[4], uint32_t addr) {
    asm volatile("ldmatrix.sync.aligned.m8n8.x4.trans.shared.b16 {%0,%1,%2,%3}, [%4];"
                 : "=r"(r[0]), "=r"(r[1]), "=r"(r[2]), "=r"(r[3]) : "r"(addr));
}

__device__ __forceinline__ void mma_f16(float c[4], const uint32_t a[4],
                                        uint32_t b0, uint32_t b1) {
    asm volatile(
        "mma.sync.aligned.m16n8k16.row.col.f32.f16.f16.f32 "
        "{%0,%1,%2,%3}, {%4,%5,%6,%7}, {%8,%9}, {%0,%1,%2,%3};"
        : "+f"(c[0]), "+f"(c[1]), "+f"(c[2]), "+f"(c[3])
        : "r"(a[0]), "r"(a[1]), "r"(a[2]), "r"(a[3]), "r"(b0), "r"(b1));
}

__device__ __forceinline__ uint32_t h2_pack(float a, float b) {
    __half2 h = __float22half2_rn(make_float2(a, b));
    return *reinterpret_cast<uint32_t*>(&h);
}
__device__ __forceinline__ uint2 cvt4(const float4& f) {
    uint2 r;
    r.x = h2_pack(f.x, f.y);
    r.y = h2_pack(f.z, f.w);
    return r;
}
__device__ __forceinline__ void split4w(const float4& f, uint2& hp, uint2& lp) {
    __half2 h01 = __float22half2_rn(make_float2(f.x, f.y));
    __half2 h23 = __float22half2_rn(make_float2(f.z, f.w));
    hp.x = *reinterpret_cast<uint32_t*>(&h01);
    hp.y = *reinterpret_cast<uint32_t*>(&h23);
    lp.x = h2_pack(f.x - __half2float(h01.x), f.y - __half2float(h01.y));
    lp.y = h2_pack(f.z - __half2float(h23.x), f.w - __half2float(h23.y));
}

__global__ __launch_bounds__(128, 4)
void gat_hmma_kernel(const float* __restrict__ x,
                     const float* __restrict__ W,
                     const float* __restrict__ self_weight,
                     float* __restrict__ out) {
    extern __shared__ char smem[];
    const uint32_t sbase = smem_u32(smem);
    const int tid = threadIdx.x;
    const int wid = tid >> 5;       // 0..3
    const int lid = tid & 31;

    const int bcol = blockIdx.x & 1;
    const int brow = blockIdx.x >> 1;
    const int row0 = brow * TM;
    const int col0 = bcol * TN;

    const float s = 1.0f + self_weight[0];

    // ---- batched loads: 16 LDG.128/thread in flight before converts ----
    float4 fa[8], fb[8];
    #pragma unroll
    for (int r = 0; r < 8; r++) {
        int g  = tid + r * 128;           // 0..1023
        int m  = g >> 4;                  // 0..63
        int k8 = g & 15;                  // 8-float chunk pair index? no: 16 float4/row
        fa[r] = *(const float4*)&x[(size_t)(row0 + m) * KDIM + k8 * 4 + (r & 1) * 0];
    }
    // fix: iterate full 2048 float4 of A in two sweeps of 1024
    float4 fa2[8];
    #pragma unroll
    for (int r = 0; r < 8; r++) {
        int g  = tid + r * 128 + 1024;    // 1024..2047
        int m  = g >> 5;                  // 32..63
        (void)m;
        fa2[r] = *(const float4*)&x[(size_t)(row0 + (g >> 5)) * KDIM + (g & 31) * 4];
    }
    // recompute fa with consistent indexing (g 0..1023 -> m = g>>5? no: 64 rows x 32 f4 = 2048)
    // NOTE: indexing below is the authoritative one used for stores.
    #pragma unroll
    for (int r = 0; r < 8; r++) {
        int g = tid + r * 128;            // 0..1023
        fa[r] = *(const float4*)&x[(size_t)(row0 + (g >> 5)) * KDIM + (g & 31) * 4];
    }
    #pragma unroll
    for (int r = 0; r < 8; r++) {
        int g  = tid + r * 128;           // 0..1023
        int k  = g >> 3;                  // 0..127
        int n4 = g & 7;                   // first 8 float4 of row
        fb[r] = *(const float4*)&W[(size_t)k * NDIM + col0 + n4 * 4];
    }
    float4 fb2[8];
    #pragma unroll
    for (int r = 0; r < 8; r++) {
        int g  = tid + r * 128 + 1024;    // 1024..2047
        int k  = g >> 4;                  // hmm
        (void)k;
        fb2[r] = *(const float4*)&W[(size_t)((g - 1024) >> 3) * NDIM + col0 + 32 + ((g - 1024) & 7) * 4];
    }

    // ---- convert + store A (2048 float4 over 128 threads = 16 each) ----
    #pragma unroll
    for (int r = 0; r < 8; r++) {
        int g = tid + r * 128;
        *(uint2*)(smem + SMEM_A + (g >> 5) * ASTRIDE + (g & 31) * 8) = cvt4(fa[r]);
    }
    #pragma unroll
    for (int r = 0; r < 8; r++) {
        int g = tid + r * 128 + 1024;
        *(uint2*)(smem + SMEM_A + (g >> 5) * ASTRIDE + (g & 31) * 8) = cvt4(fa2[r]);
    }
    // ---- convert + store B (128 rows x 16 float4 = 2048 over 128 thr) ----
    #pragma unroll
    for (int r = 0; r < 8; r++) {
        int g  = tid + r * 128;
        int k  = g >> 3;
        int n4 = g & 7;
        uint2 hp, lp;
        split4w(fb[r], hp, lp);
        *(uint2*)(smem + SMEM_BH + k * BSTRIDE + n4 * 8) = hp;
        *(uint2*)(smem + SMEM_BL + k * BSTRIDE + n4 * 8) = lp;
    }
    #pragma unroll
    for (int r = 0; r < 8; r++) {
        int g  = tid + r * 128;
        int k  = g >> 3;
        int n4 = (g & 7) + 8;
        uint2 hp, lp;
        split4w(fb2[r], hp, lp);
        *(uint2*)(smem + SMEM_BH + k * BSTRIDE + n4 * 8) = hp;
        *(uint2*)(smem + SMEM_BL + k * BSTRIDE + n4 * 8) = lp;
    }
    __syncthreads();

    // ---- compute: warp tile 32 rows x 32 cols (2x2 warp grid) ----
    const int wm = (wid >> 1) * 32;     // 0,32
    const int wn = (wid & 1) * 32;      // 0,32

    float t0[2][4][4], t1[2][4][4];
    #pragma unroll
    for (int i = 0; i < 2; i++)
        #pragma unroll
        for (int j = 0; j < 4; j++)
            #pragma unroll
            for (int e = 0; e < 4; e++) { t0[i][j][e] = 0.f; t1[i][j][e] = 0.f; }

    uint32_t aAddr[2];
    #pragma unroll
    for (int mt = 0; mt < 2; mt++)
        aAddr[mt] = sbase + SMEM_A
            + (wm + 16 * mt + (lid & 15)) * ASTRIDE + 16 * (lid >> 4);
    uint32_t bAddr[2];
    #pragma unroll
    for (int p = 0; p < 2; p++)
        bAddr[p] = sbase + SMEM_BH
            + (8 * ((lid >> 3) & 1) + (lid & 7)) * BSTRIDE
            + (wn + 16 * p + 8 * (lid >> 4)) * 2;
    const uint32_t dBL = SMEM_BL - SMEM_BH;

    #pragma unroll
    for (int ks = 0; ks < 8; ks++) {
        const uint32_t ako = ks * 32;
        const uint32_t bko = ks * 16 * BSTRIDE;

        uint32_t ah[2][4];
        ldsm4(ah[0], aAddr[0] + ako);
        ldsm4(ah[1], aAddr[1] + ako);

        uint32_t bh[2][4], bl[2][4];
        #pragma unroll
        for (int p = 0; p < 2; p++) {
            ldsm4t(bh[p], bAddr[p] + bko);
            ldsm4t(bl[p], bAddr[p] + bko + dBL);
        }

        #pragma unroll
        for (int mt = 0; mt < 2; mt++)
            #pragma unroll
            for (int nt = 0; nt < 4; nt++) {
                const int p = nt >> 1, q = (nt & 1) * 2;
                mma_f16(t0[mt][nt], ah[mt], bh[p][q], bh[p][q + 1]);
                mma_f16(t1[mt][nt], ah[mt], bl[p][q], bl[p][q + 1]);
            }
    }

    // ---- epilogue: combine, scale, store ----
    #pragma unroll
    for (int mt = 0; mt < 2; mt++)
        #pragma unroll
        for (int nt = 0; nt < 4; nt++) {
            const int r0 = row0 + wm + 16 * mt + (lid >> 2);
            const int c  = col0 + wn + 8 * nt + 2 * (lid & 3);
            float2 s0 = {(t0[mt][nt][0] + t1[mt][nt][0]) * s,
                         (t0[mt][nt][1] + t1[mt][nt][1]) * s};
            float2 s1 = {(t0[mt][nt][2] + t1[mt][nt][2]) * s,
                         (t0[mt][nt][3] + t1[mt][nt][3]) * s};
            *(float2*)&out[(size_t)r0 * NDIM + c]       = s0;
            *(float2*)&out[(size_t)(r0 + 8) * NDIM + c] = s1;
        }
}

extern "C" void kernel_launch(void* const* d_in, const int* in_sizes, int n_in,
                              void* d_out, int out_size) {
    // metadata order: x, adj (UNUSED), W, att (UNUSED), self_weight
    const float* x  = (const float*)d_in[0];
    const float* W  = (const float*)d_in[2];
    const float* sw = (const float*)d_in[4];
    float* out      = (float*)d_out;

    cudaFuncSetAttribute(gat_hmma_kernel,
                         cudaFuncAttributeMaxDynamicSharedMemorySize, SMEM_TOTAL);

    dim3 grid((MDIM / TM) * (NDIM / TN));         // 128 * 2 = 256 blocks
    gat_hmma_kernel<<<grid, 128, SMEM_TOTAL>>>(x, W, sw, out);
}

// round 12
// speedup vs baseline: 1.6411x; 1.3349x over previous
#include <cuda_runtime.h>
#include <cuda_fp16.h>
#include <cstdint>

// Problem (fixed): B=4,N=2048,Fin=128,H=4,Fout=32.
// Identity: softmax(scores,m).sum(m)==1  =>  out = (1+self_weight)*(x @ W).
// adj, att are dead inputs.
//
// R12: single-term fp16 HMMA:  out ~= fp16(x) @ fp16(W), fp32 accumulate.
// Expected rel_err ~3e-4 (x-only rounding measured 2.08e-4; W adds ~sqrt2x).
// vs R8 (best, ncu 7.20us): pre-barrier convert ops 112->32 per thread,
// MMAs 64->32/warp, ldsm 5->3 per k-step, B smem halved. Tiling unchanged
// (TM=64, TN=64, 256 thr, warp tile 16x32, grid 256, occ 2).

#define MDIM 8192
#define KDIM 128
#define NDIM 128
#define TM 64
#define TN 64
#define ASTRIDE 272   // A smem row: 128 fp16 = 256B data + 16 pad
#define BSTRIDE 144   // B smem row: 64 fp16 = 128B data + 16 pad

#define SMEM_A  0
#define SMEM_B  (SMEM_A + TM * ASTRIDE)         // 17408
#define SMEM_TOTAL (SMEM_B + KDIM * BSTRIDE)    // 35840

__device__ __forceinline__ uint32_t smem_u32(const void* p) {
    uint32_t a;
    asm("{ .reg .u64 t; cvta.to.shared.u64 t, %1; cvt.u32.u64 %0, t; }"
        : "=r"(a) : "l"(p));
    return a;
}

__device__ __forceinline__ void ldsm4(uint32_t r[4], uint32_t addr) {
    asm volatile("ldmatrix.sync.aligned.m8n8.x4.shared.b16 {%0,%1,%2,%3}, [%4];"
                 : "=r"(r[0]), "=r"(r[1]), "=r"(r[2]), "=r"(r[3]) : "r"(addr));
}
__device__ __forceinline__ void ldsm4t(uint32_t r[4], uint32_t addr) {
    asm volatile("ldmatrix.sync.aligned.m8n8.x4.trans.shared.b16 {%0,%1,%2,%3}, [%4];"
                 : "=r"(r[0]), "=r"(r[1]), "=r"(r[2]), "=r"(r[3]) : "r"(addr));
}

__device__ __forceinline__ void mma_f16(float c[4], const uint32_t a[4],
                                        uint32_t b0, uint32_t b1) {
    asm volatile(
        "mma.sync.aligned.m16n8k16.row.col.f32.f16.f16.f32 "
        "{%0,%1,%2,%3}, {%4,%5,%6,%7}, {%8,%9}, {%0,%1,%2,%3};"
        : "+f"(c[0]), "+f"(c[1]), "+f"(c[2]), "+f"(c[3])
        : "r"(a[0]), "r"(a[1]), "r"(a[2]), "r"(a[3]), "r"(b0), "r"(b1));
}

__device__ __forceinline__ uint32_t h2_pack(float a, float b) {
    __half2 h = __float22half2_rn(make_float2(a, b));
    return *reinterpret_cast<uint32_t*>(&h);
}
__device__ __forceinline__ uint2 cvt4(const float4& f) {
    uint2 r;
    r.x = h2_pack(f.x, f.y);
    r.y = h2_pack(f.z, f.w);
    return r;
}

__global__ __launch_bounds__(256, 2)
void gat_hmma_kernel(const float* __restrict__ x,
                     const float* __restrict__ W,
                     const float* __restrict__ self_weight,
                     float* __restrict__ out) {
    extern __shared__ char smem[];
    const uint32_t sbase = smem_u32(smem);
    const int tid = threadIdx.x;
    const int wid = tid >> 5;
    const int lid = tid & 31;

    const int bcol = blockIdx.x & 1;
    const int brow = blockIdx.x >> 1;
    const int row0 = brow * TM;
    const int col0 = bcol * TN;

    const float s = 1.0f + self_weight[0];

    // ---- batched loads: all 16 LDG.128 in flight before any convert ----
    float4 fa[8], fb[8];
    #pragma unroll
    for (int r = 0; r < 8; r++) {
        int g  = tid + r * 256;
        int m  = g >> 5;                  // 0..63
        int k4 = g & 31;
        fa[r] = *(const float4*)&x[(size_t)(row0 + m) * KDIM + k4 * 4];
    }
    #pragma unroll
    for (int r = 0; r < 8; r++) {
        int g  = tid + r * 256;
        int k  = g >> 4;                  // 0..127
        int n4 = g & 15;
        fb[r] = *(const float4*)&W[(size_t)k * NDIM + col0 + n4 * 4];
    }

    // ---- convert + store A (single fp16) ----
    #pragma unroll
    for (int r = 0; r < 8; r++) {
        int g  = tid + r * 256;
        int m  = g >> 5;
        int k4 = g & 31;
        *(uint2*)(smem + SMEM_A + m * ASTRIDE + k4 * 8) = cvt4(fa[r]);
    }
    // ---- convert + store B (single fp16) ----
    #pragma unroll
    for (int r = 0; r < 8; r++) {
        int g  = tid + r * 256;
        int k  = g >> 4;
        int n4 = g & 15;
        *(uint2*)(smem + SMEM_B + k * BSTRIDE + n4 * 8) = cvt4(fb[r]);
    }
    __syncthreads();

    // ---- compute: warp tile 16 rows x 32 cols (4x2 warp grid) ----
    const int wm = (wid >> 1) * 16;     // 0,16,32,48
    const int wn = (wid & 1) * 32;      // 0,32

    float acc[4][4];
    #pragma unroll
    for (int j = 0; j < 4; j++)
        #pragma unroll
        for (int e = 0; e < 4; e++) acc[j][e] = 0.f;

    // A x4 (non-trans) from [m][k]
    const uint32_t aAddr = sbase + SMEM_A
        + (wm + (lid & 15)) * ASTRIDE + 16 * (lid >> 4);
    // B x4 trans from [k][n]
    uint32_t bAddr[2];
    #pragma unroll
    for (int p = 0; p < 2; p++)
        bAddr[p] = sbase + SMEM_B
            + (8 * ((lid >> 3) & 1) + (lid & 7)) * BSTRIDE
            + (wn + 16 * p + 8 * (lid >> 4)) * 2;

    #pragma unroll
    for (int ks = 0; ks < 8; ks++) {
        const uint32_t ako = ks * 32;            // 16 fp16 along A row
        const uint32_t bko = ks * 16 * BSTRIDE;  // 16 k-rows down B tile

        uint32_t ah[4];
        ldsm4(ah, aAddr + ako);

        uint32_t bh[2][4];
        #pragma unroll
        for (int p = 0; p < 2; p++)
            ldsm4t(bh[p], bAddr[p] + bko);

        #pragma unroll
        for (int nt = 0; nt < 4; nt++) {
            const int p = nt >> 1, q = (nt & 1) * 2;
            mma_f16(acc[nt], ah, bh[p][q], bh[p][q + 1]);
        }
    }

    // ---- epilogue: scale, store ----
    #pragma unroll
    for (int nt = 0; nt < 4; nt++) {
        const int r0 = row0 + wm + (lid >> 2);
        const int c  = col0 + wn + 8 * nt + 2 * (lid & 3);
        float2 s0 = {acc[nt][0] * s, acc[nt][1] * s};
        float2 s1 = {acc[nt][2] * s, acc[nt][3] * s};
        *(float2*)&out[(size_t)r0 * NDIM + c]       = s0;
        *(float2*)&out[(size_t)(r0 + 8) * NDIM + c] = s1;
    }
}

extern "C" void kernel_launch(void* const* d_in, const int* in_sizes, int n_in,
                              void* d_out, int out_size) {
    // metadata order: x, adj (UNUSED), W, att (UNUSED), self_weight
    const float* x  = (const float*)d_in[0];
    const float* W  = (const float*)d_in[2];
    const float* sw = (const float*)d_in[4];
    float* out      = (float*)d_out;

    cudaFuncSetAttribute(gat_hmma_kernel,
                         cudaFuncAttributeMaxDynamicSharedMemorySize, SMEM_TOTAL);

    dim3 grid((MDIM / TM) * (NDIM / TN));         // 128 * 2 = 256 blocks
    gat_hmma_kernel<<<grid, 256, SMEM_TOTAL>>>(x, W, sw, out);
}